// round 10
// baseline (speedup 1.0000x reference)
#include <cuda_runtime.h>
#include <cuda_fp16.h>
#include <math.h>

#define NN 100000
#define EE 800000
#define DF 128
#define NB 391          // (NN+255)/256
#define FULLM 0xFFFFFFFFu

// ---------- scratch (no cudaMalloc allowed) ----------
__device__ __align__(16) __half2 g_hs[NN * (DF / 2)];  // h = x@W1 fp16 (25.6 MB)
__device__ __half  g_Wt[DF * DF];        // W1 transposed, fp16: [n][k]
__device__ float2 g_gs[NN];              // gs = (h2@W2)*dinv[row]
__device__ float  g_dinv[NN];
__device__ int    g_cnt[NN];             // in-degree (no self loop)
__device__ int    g_rowstart[NN];        // CSR offsets (by dst)
__device__ int    g_pos[NN];             // binning cursor
__device__ int    g_esrc[EE];            // src node per CSR slot
__device__ int    g_aggv[NB];            // lookback: block aggregate
__device__ int    g_incv[NB];            // lookback: inclusive prefix
__device__ int    g_flag[NB];            // lookback: 0=none,1=agg,2=inclusive

// ---------- side stream for GEMM overlap ----------
static cudaStream_t g_s2;
static cudaEvent_t g_ev1, g_ev2;
static struct StreamInit {
    StreamInit() {
        cudaStreamCreateWithFlags(&g_s2, cudaStreamNonBlocking);
        cudaEventCreateWithFlags(&g_ev1, cudaEventDisableTiming);
        cudaEventCreateWithFlags(&g_ev2, cudaEventDisableTiming);
    }
} g_stream_init;

// ---------- zero degree counts (int4) + reset lookback flags ----------
__global__ void k_zero_cnt() {
    int i = blockIdx.x * blockDim.x + threadIdx.x;
    if (i < NN / 4) ((int4*)g_cnt)[i] = make_int4(0, 0, 0, 0);
    if (i < NB) g_flag[i] = 0;
}

// ---------- degree count: 4 edges per thread (int4 reads) ----------
__global__ void k_count(const int* __restrict__ dst) {
    int e4 = blockIdx.x * blockDim.x + threadIdx.x;
    if (e4 < EE / 4) {
        int4 d = ((const int4*)dst)[e4];
        atomicAdd(&g_cnt[d.x], 1);
        atomicAdd(&g_cnt[d.y], 1);
        atomicAdd(&g_cnt[d.z], 1);
        atomicAdd(&g_cnt[d.w], 1);
    }
}

// ---------- single-pass scan (decoupled lookback) + dinv + pos ----------
__global__ __launch_bounds__(256) void k_scan() {
    __shared__ int sh_warp[8];
    __shared__ int sh_prefix;
    int b = blockIdx.x, t = threadIdx.x, i = b * 256 + t;
    int lane = t & 31, wid = t >> 5;
    int v = (i < NN) ? g_cnt[i] : 0;

    int s = v;
#pragma unroll
    for (int o = 1; o < 32; o <<= 1) {
        int x = __shfl_up_sync(FULLM, s, o);
        if (lane >= o) s += x;
    }
    if (lane == 31) sh_warp[wid] = s;
    __syncthreads();
    if (t < 8) {
        int ws = sh_warp[t];
#pragma unroll
        for (int o = 1; o < 8; o <<= 1) {
            int x = __shfl_up_sync(0xFFu, ws, o);
            if (t >= o) ws += x;
        }
        sh_warp[t] = ws;
    }
    __syncthreads();
    int incl = s + (wid ? sh_warp[wid - 1] : 0);
    int btot = sh_warp[7];

    if (t == 0) {
        g_aggv[b] = btot;
        __threadfence();
        ((volatile int*)g_flag)[b] = 1;
    }

    if (t < 32) {
        int running = 0;
        if (b > 0) {
            int base = b - 1;
            while (true) {
                int idx = base - t;
                int f;
                do {
                    f = (idx >= 0) ? ((volatile int*)g_flag)[idx] : 2;
                } while (__ballot_sync(FULLM, f == 0));
                __threadfence();
                unsigned m2 = __ballot_sync(FULLM, f == 2);
                int val = 0;
                if (m2) {
                    int L = __ffs(m2) - 1;
                    if (t < L) val = ((volatile int*)g_aggv)[idx];
                    else if (t == L) val = (idx >= 0) ? ((volatile int*)g_incv)[idx] : 0;
                } else {
                    val = ((volatile int*)g_aggv)[idx];
                }
#pragma unroll
                for (int o = 16; o > 0; o >>= 1) val += __shfl_xor_sync(FULLM, val, o);
                running += val;
                if (m2) break;
                base -= 32;
            }
        }
        if (t == 0) {
            g_incv[b] = running + btot;
            __threadfence();
            ((volatile int*)g_flag)[b] = 2;
            sh_prefix = running;
        }
    }
    __syncthreads();

    if (i < NN) {
        int rs = sh_prefix + incl - v;
        g_rowstart[i] = rs;
        g_pos[i] = rs;
        g_dinv[i] = rsqrtf(1.0f + (float)v);
    }
}

// ---------- bin edges into CSR: 4 edges per thread (int4 reads) ----------
__global__ void k_bin(const int* __restrict__ src, const int* __restrict__ dst) {
    int e4 = blockIdx.x * blockDim.x + threadIdx.x;
    if (e4 < EE / 4) {
        int4 d = ((const int4*)dst)[e4];
        int4 s = ((const int4*)src)[e4];
        g_esrc[atomicAdd(&g_pos[d.x], 1)] = s.x;
        g_esrc[atomicAdd(&g_pos[d.y], 1)] = s.y;
        g_esrc[atomicAdd(&g_pos[d.z], 1)] = s.z;
        g_esrc[atomicAdd(&g_pos[d.w], 1)] = s.w;
    }
}

// ---------- W1 transpose + fp16 convert: g_Wt[n][k] = fp16(W1[k][n]) ----------
__global__ void k_wprep(const float* __restrict__ W1) {
    int tid = blockIdx.x * 256 + threadIdx.x;   // 16384
    int n = tid >> 7, k = tid & 127;
    g_Wt[n * DF + k] = __float2half(W1[(size_t)k * DF + n]);
}

// ---------- fp16 tensor-core GEMM1: g_hs = fp16(x @ W1) ----------
__device__ __forceinline__ void mma_f16(float* c, const unsigned* a, const unsigned* b) {
    asm volatile(
        "mma.sync.aligned.m16n8k16.row.col.f32.f16.f16.f32 "
        "{%0,%1,%2,%3}, {%4,%5,%6,%7}, {%8,%9}, {%0,%1,%2,%3};"
        : "+f"(c[0]), "+f"(c[1]), "+f"(c[2]), "+f"(c[3])
        : "r"(a[0]), "r"(a[1]), "r"(a[2]), "r"(a[3]), "r"(b[0]), "r"(b[1]));
}

#define XS_STR 40
#define WS_STR 136

__global__ __launch_bounds__(256, 2) void k_gemm1(const float* __restrict__ X) {
    __shared__ __half Xs[128][XS_STR];
    __shared__ __half Ws[128][WS_STR];

    const int t = threadIdx.x;
    const int m0 = blockIdx.x * 128;
    const int w = t >> 5, lane = t & 31;
    const int m0w = (w >> 2) * 64;
    const int n0w = (w & 3) * 32;
    const int lg = lane >> 2, lq = lane & 3;

#pragma unroll
    for (int i = 0; i < 8; i++) {
        int g = i * 256 + t;
        int row = g >> 4, c = (g & 15) * 8;
        *(uint4*)&Ws[row][c] = *(const uint4*)&g_Wt[row * DF + c];
    }

    float acc[4][4][4] = {};
    float4 pv[4];

    auto prefetch = [&](int kc) {
#pragma unroll
        for (int i = 0; i < 4; i++) {
            int g = i * 256 + t;
            int row = g >> 3, q = g & 7;
            int m = m0 + row;
            pv[i] = (m < NN) ? *(const float4*)&X[(size_t)m * DF + kc * 32 + q * 4]
                             : make_float4(0.f, 0.f, 0.f, 0.f);
        }
    };

    prefetch(0);
    __syncthreads();

    for (int kc = 0; kc < 4; kc++) {
#pragma unroll
        for (int i = 0; i < 4; i++) {
            int g = i * 256 + t;
            int row = g >> 3, q = g & 7;
            __half2 h0 = __floats2half2_rn(pv[i].x, pv[i].y);
            __half2 h1 = __floats2half2_rn(pv[i].z, pv[i].w);
            uint2 u;
            u.x = *(unsigned*)&h0;
            u.y = *(unsigned*)&h1;
            *(uint2*)&Xs[row][q * 4] = u;
        }
        __syncthreads();
        if (kc < 3) prefetch(kc + 1);

#pragma unroll
        for (int k0 = 0; k0 < 32; k0 += 16) {
            int kg = kc * 32 + k0;
            unsigned A[4][4], B[4][2];
#pragma unroll
            for (int mi = 0; mi < 4; mi++) {
                int mr = m0w + mi * 16 + lg;
                A[mi][0] = *(unsigned*)&Xs[mr][k0 + 2 * lq];
                A[mi][1] = *(unsigned*)&Xs[mr + 8][k0 + 2 * lq];
                A[mi][2] = *(unsigned*)&Xs[mr][k0 + 8 + 2 * lq];
                A[mi][3] = *(unsigned*)&Xs[mr + 8][k0 + 8 + 2 * lq];
            }
#pragma unroll
            for (int ni = 0; ni < 4; ni++) {
                int nc = n0w + ni * 8 + lg;
                B[ni][0] = *(unsigned*)&Ws[nc][kg + 2 * lq];
                B[ni][1] = *(unsigned*)&Ws[nc][kg + 8 + 2 * lq];
            }
#pragma unroll
            for (int mi = 0; mi < 4; mi++)
#pragma unroll
                for (int ni = 0; ni < 4; ni++)
                    mma_f16(acc[mi][ni], A[mi], B[ni]);
        }
        __syncthreads();
    }

#pragma unroll
    for (int mi = 0; mi < 4; mi++) {
        int r0 = m0 + m0w + mi * 16 + lg;
        int r1 = r0 + 8;
#pragma unroll
        for (int ni = 0; ni < 4; ni++) {
            int h2col = ((n0w + ni * 8) >> 1) + lq;
            if (r0 < NN)
                g_hs[(size_t)r0 * (DF / 2) + h2col] =
                    __floats2half2_rn(acc[mi][ni][0], acc[mi][ni][1]);
            if (r1 < NN)
                g_hs[(size_t)r1 * (DF / 2) + h2col] =
                    __floats2half2_rn(acc[mi][ni][2], acc[mi][ni][3]);
        }
    }
}

// ---------- fused gather-aggregate + relu + W2 GEMV (layer 1 -> gs) ----------
// one warp per dst node; paired edges: lanes 0-15 edge j, lanes 16-31 edge j+1.
// Each lane holds 8 features (uint4 = 16B of the 256B row).
__global__ __launch_bounds__(256) void k_agg_mid(const float* __restrict__ b1,
                                                 const float* __restrict__ W2) {
    int gt = blockIdx.x * 256 + threadIdx.x;
    int r = gt >> 5, lane = gt & 31;
    if (r >= NN) return;

    const uint4* hsv = (const uint4*)g_hs;   // 16 uint4 per row
    const int half = lane >> 4, fl = lane & 15;
    float di = g_dinv[r];

    float acc[8] = {0.f, 0.f, 0.f, 0.f, 0.f, 0.f, 0.f, 0.f};
    if (half == 0) {   // self term on low half
        uint4 sv = hsv[(size_t)r * 16 + fl];
        float2 f0 = __half22float2(*(__half2*)&sv.x);
        float2 f1 = __half22float2(*(__half2*)&sv.y);
        float2 f2 = __half22float2(*(__half2*)&sv.z);
        float2 f3 = __half22float2(*(__half2*)&sv.w);
        acc[0] = f0.x * di; acc[1] = f0.y * di;
        acc[2] = f1.x * di; acc[3] = f1.y * di;
        acc[4] = f2.x * di; acc[5] = f2.y * di;
        acc[6] = f3.x * di; acc[7] = f3.y * di;
    }

    int start = g_rowstart[r];
    int len = g_cnt[r];
    for (int j0 = 0; j0 < len; j0 += 32) {
        int cnt = min(32, len - j0);
        int sidx = 0;
        float sd = 0.f;
        if (lane < cnt) {
            sidx = g_esrc[start + j0 + lane];
            sd = g_dinv[sidx];
        }
#pragma unroll 4
        for (int j = 0; j < cnt; j += 2) {
            int s0 = __shfl_sync(FULLM, sidx, j);
            float d0 = __shfl_sync(FULLM, sd, j);
            int s1 = __shfl_sync(FULLM, sidx, j + 1);   // j+1 <= 31
            float d1 = __shfl_sync(FULLM, sd, j + 1);   // sd==0 past cnt
            int s = half ? s1 : s0;
            float d = half ? d1 : d0;
            uint4 v = hsv[(size_t)s * 16 + fl];
            float2 f0 = __half22float2(*(__half2*)&v.x);
            float2 f1 = __half22float2(*(__half2*)&v.y);
            float2 f2 = __half22float2(*(__half2*)&v.z);
            float2 f3 = __half22float2(*(__half2*)&v.w);
            acc[0] = fmaf(f0.x, d, acc[0]); acc[1] = fmaf(f0.y, d, acc[1]);
            acc[2] = fmaf(f1.x, d, acc[2]); acc[3] = fmaf(f1.y, d, acc[3]);
            acc[4] = fmaf(f2.x, d, acc[4]); acc[5] = fmaf(f2.y, d, acc[5]);
            acc[6] = fmaf(f3.x, d, acc[6]); acc[7] = fmaf(f3.y, d, acc[7]);
        }
    }

    // fold odd-edge half into low half
#pragma unroll
    for (int i = 0; i < 8; i++) acc[i] += __shfl_down_sync(FULLM, acc[i], 16);

    if (half == 0) {
        float4 bb0 = *(const float4*)&b1[fl * 8];
        float4 bb1 = *(const float4*)&b1[fl * 8 + 4];
        float h[8];
        h[0] = fmaxf(fmaf(di, acc[0], bb0.x), 0.f);
        h[1] = fmaxf(fmaf(di, acc[1], bb0.y), 0.f);
        h[2] = fmaxf(fmaf(di, acc[2], bb0.z), 0.f);
        h[3] = fmaxf(fmaf(di, acc[3], bb0.w), 0.f);
        h[4] = fmaxf(fmaf(di, acc[4], bb1.x), 0.f);
        h[5] = fmaxf(fmaf(di, acc[5], bb1.y), 0.f);
        h[6] = fmaxf(fmaf(di, acc[6], bb1.z), 0.f);
        h[7] = fmaxf(fmaf(di, acc[7], bb1.w), 0.f);

        float gx = 0.f, gy = 0.f;
#pragma unroll
        for (int i = 0; i < 8; i++) {
            float2 wv = *(const float2*)&W2[(size_t)(fl * 8 + i) * 2];
            gx = fmaf(h[i], wv.x, gx);
            gy = fmaf(h[i], wv.y, gy);
        }
#pragma unroll
        for (int off = 8; off > 0; off >>= 1) {
            gx += __shfl_xor_sync(0x0000FFFFu, gx, off);
            gy += __shfl_xor_sync(0x0000FFFFu, gy, off);
        }
        if (fl == 0) g_gs[r] = make_float2(gx * di, gy * di);
    }
}

// ---------- layer-2 gather + bias -> out ----------
__global__ __launch_bounds__(256) void k_agg2(const float* __restrict__ b2,
                                              float* __restrict__ out) {
    int gt = blockIdx.x * 256 + threadIdx.x;
    int r = gt >> 5, lane = gt & 31;
    if (r >= NN) return;

    int start = g_rowstart[r];
    int len = g_cnt[r];
    float ax = 0.f, ay = 0.f;
    for (int j = lane; j < len; j += 32) {
        int s = g_esrc[start + j];
        float2 v = g_gs[s];
        ax += v.x; ay += v.y;
    }
#pragma unroll
    for (int off = 16; off > 0; off >>= 1) {
        ax += __shfl_xor_sync(FULLM, ax, off);
        ay += __shfl_xor_sync(FULLM, ay, off);
    }
    if (lane == 0) {
        float di = g_dinv[r];
        float2 self = g_gs[r];
        float2 o = make_float2(fmaf(di, self.x + ax, __ldg(&b2[0])),
                               fmaf(di, self.y + ay, __ldg(&b2[1])));
        *(float2*)&out[(size_t)r * 2] = o;
    }
}

extern "C" void kernel_launch(void* const* d_in, const int* in_sizes, int n_in,
                              void* d_out, int out_size) {
    const float* x  = (const float*)d_in[0];
    const int*   ei = (const int*)d_in[1];
    const float* W1 = (const float*)d_in[2];
    const float* b1 = (const float*)d_in[3];
    const float* W2 = (const float*)d_in[4];
    const float* b2 = (const float*)d_in[5];
    const int* src = ei;        // edge_index[0, :]
    const int* dst = ei + EE;   // edge_index[1, :]

    // fork point for side stream
    cudaEventRecord(g_ev1, 0);
    cudaStreamWaitEvent(g_s2, g_ev1, 0);

    // CSR build chain on main stream
    k_zero_cnt<<<(NN / 4 + 255) / 256, 256>>>();
    k_count<<<(EE / 4 + 255) / 256, 256>>>(dst);
    k_scan<<<NB, 256>>>();
    k_bin<<<(EE / 4 + 255) / 256, 256>>>(src, dst);

    // GEMM branch on side stream (overlaps CSR chain)
    k_wprep<<<64, 256, 0, g_s2>>>(W1);
    k_gemm1<<<(NN + 127) / 128, 256, 0, g_s2>>>(x);
    cudaEventRecord(g_ev2, g_s2);

    // join, then fused aggregation
    cudaStreamWaitEvent(0, g_ev2, 0);
    k_agg_mid<<<(NN * 32 + 255) / 256, 256>>>(b1, W2);
    k_agg2<<<(NN * 32 + 255) / 256, 256>>>(b2, (float*)d_out);
}

// round 11
// speedup vs baseline: 1.0703x; 1.0703x over previous
#include <cuda_runtime.h>
#include <cuda_fp16.h>
#include <math.h>

#define NN 100000
#define EE 800000
#define DF 128
#define NB 391          // (NN+255)/256
#define FULLM 0xFFFFFFFFu

// ---------- scratch (no cudaMalloc allowed) ----------
__device__ __align__(16) __half2 g_hs[NN * (DF / 2)];  // h = x@W1 fp16 (25.6 MB)
__device__ __half  g_Wt[DF * DF];        // W1 transposed, fp16: [n][k]
__device__ float2 g_gs[NN];              // gs = (h2@W2)*dinv[row]
__device__ float  g_dinv[NN];
__device__ int    g_cnt[NN];             // in-degree (no self loop)
__device__ int    g_rowstart[NN];        // CSR offsets (by dst)
__device__ int    g_pos[NN];             // binning cursor
__device__ int    g_esrc[EE];            // src node per CSR slot
__device__ int    g_aggv[NB];            // lookback: block aggregate
__device__ int    g_incv[NB];            // lookback: inclusive prefix
__device__ int    g_flag[NB];            // lookback: 0=none,1=agg,2=inclusive

// ---------- side stream for GEMM overlap ----------
static cudaStream_t g_s2;
static cudaEvent_t g_ev1, g_ev2;
static struct StreamInit {
    StreamInit() {
        cudaStreamCreateWithFlags(&g_s2, cudaStreamNonBlocking);
        cudaEventCreateWithFlags(&g_ev1, cudaEventDisableTiming);
        cudaEventCreateWithFlags(&g_ev2, cudaEventDisableTiming);
    }
} g_stream_init;

// ---------- degree ----------
__global__ void k_zero_cnt() {
    int i = blockIdx.x * blockDim.x + threadIdx.x;
    if (i < NN) g_cnt[i] = 0;
}

__global__ void k_count(const int* __restrict__ dst) {
    int e = blockIdx.x * blockDim.x + threadIdx.x;
    if (e < NB) g_flag[e] = 0;               // reset lookback flags each call
    if (e < EE) atomicAdd(&g_cnt[dst[e]], 1);
}

// ---------- single-pass scan (decoupled lookback) + dinv + pos ----------
__global__ __launch_bounds__(256) void k_scan() {
    __shared__ int sh_warp[8];
    __shared__ int sh_prefix;
    int b = blockIdx.x, t = threadIdx.x, i = b * 256 + t;
    int lane = t & 31, wid = t >> 5;
    int v = (i < NN) ? g_cnt[i] : 0;

    int s = v;
#pragma unroll
    for (int o = 1; o < 32; o <<= 1) {
        int x = __shfl_up_sync(FULLM, s, o);
        if (lane >= o) s += x;
    }
    if (lane == 31) sh_warp[wid] = s;
    __syncthreads();
    if (t < 8) {
        int ws = sh_warp[t];
#pragma unroll
        for (int o = 1; o < 8; o <<= 1) {
            int x = __shfl_up_sync(0xFFu, ws, o);
            if (t >= o) ws += x;
        }
        sh_warp[t] = ws;
    }
    __syncthreads();
    int incl = s + (wid ? sh_warp[wid - 1] : 0);
    int btot = sh_warp[7];

    if (t == 0) {
        g_aggv[b] = btot;
        __threadfence();
        ((volatile int*)g_flag)[b] = 1;
    }

    if (t < 32) {
        int running = 0;
        if (b > 0) {
            int base = b - 1;
            while (true) {
                int idx = base - t;
                int f;
                do {
                    f = (idx >= 0) ? ((volatile int*)g_flag)[idx] : 2;
                } while (__ballot_sync(FULLM, f == 0));
                __threadfence();
                unsigned m2 = __ballot_sync(FULLM, f == 2);
                int val = 0;
                if (m2) {
                    int L = __ffs(m2) - 1;
                    if (t < L) val = ((volatile int*)g_aggv)[idx];
                    else if (t == L) val = (idx >= 0) ? ((volatile int*)g_incv)[idx] : 0;
                } else {
                    val = ((volatile int*)g_aggv)[idx];
                }
#pragma unroll
                for (int o = 16; o > 0; o >>= 1) val += __shfl_xor_sync(FULLM, val, o);
                running += val;
                if (m2) break;
                base -= 32;
            }
        }
        if (t == 0) {
            g_incv[b] = running + btot;
            __threadfence();
            ((volatile int*)g_flag)[b] = 2;
            sh_prefix = running;
        }
    }
    __syncthreads();

    if (i < NN) {
        int rs = sh_prefix + incl - v;
        g_rowstart[i] = rs;
        g_pos[i] = rs;
        g_dinv[i] = rsqrtf(1.0f + (float)v);
    }
}

__global__ void k_bin(const int* __restrict__ src, const int* __restrict__ dst) {
    int e = blockIdx.x * blockDim.x + threadIdx.x;
    if (e < EE) {
        int d = dst[e];
        int p = atomicAdd(&g_pos[d], 1);
        g_esrc[p] = src[e];
    }
}

// ---------- W1 transpose + fp16 convert: g_Wt[n][k] = fp16(W1[k][n]) ----------
__global__ void k_wprep(const float* __restrict__ W1) {
    int tid = blockIdx.x * 256 + threadIdx.x;   // 16384
    int n = tid >> 7, k = tid & 127;
    g_Wt[n * DF + k] = __float2half(W1[(size_t)k * DF + n]);
}

// ---------- fp16 tensor-core GEMM1: g_hs = fp16(x @ W1) ----------
__device__ __forceinline__ void mma_f16(float* c, const unsigned* a, const unsigned* b) {
    asm volatile(
        "mma.sync.aligned.m16n8k16.row.col.f32.f16.f16.f32 "
        "{%0,%1,%2,%3}, {%4,%5,%6,%7}, {%8,%9}, {%0,%1,%2,%3};"
        : "+f"(c[0]), "+f"(c[1]), "+f"(c[2]), "+f"(c[3])
        : "r"(a[0]), "r"(a[1]), "r"(a[2]), "r"(a[3]), "r"(b[0]), "r"(b[1]));
}

#define XS_STR 40
#define WS_STR 136

__global__ __launch_bounds__(256, 2) void k_gemm1(const float* __restrict__ X) {
    __shared__ __half Xs[128][XS_STR];
    __shared__ __half Ws[128][WS_STR];

    const int t = threadIdx.x;
    const int m0 = blockIdx.x * 128;
    const int w = t >> 5, lane = t & 31;
    const int m0w = (w >> 2) * 64;
    const int n0w = (w & 3) * 32;
    const int lg = lane >> 2, lq = lane & 3;

#pragma unroll
    for (int i = 0; i < 8; i++) {
        int g = i * 256 + t;
        int row = g >> 4, c = (g & 15) * 8;
        *(uint4*)&Ws[row][c] = *(const uint4*)&g_Wt[row * DF + c];
    }

    float acc[4][4][4] = {};
    float4 pv[4];

    auto prefetch = [&](int kc) {
#pragma unroll
        for (int i = 0; i < 4; i++) {
            int g = i * 256 + t;
            int row = g >> 3, q = g & 7;
            int m = m0 + row;
            pv[i] = (m < NN) ? *(const float4*)&X[(size_t)m * DF + kc * 32 + q * 4]
                             : make_float4(0.f, 0.f, 0.f, 0.f);
        }
    };

    prefetch(0);
    __syncthreads();

    for (int kc = 0; kc < 4; kc++) {
#pragma unroll
        for (int i = 0; i < 4; i++) {
            int g = i * 256 + t;
            int row = g >> 3, q = g & 7;
            __half2 h0 = __floats2half2_rn(pv[i].x, pv[i].y);
            __half2 h1 = __floats2half2_rn(pv[i].z, pv[i].w);
            uint2 u;
            u.x = *(unsigned*)&h0;
            u.y = *(unsigned*)&h1;
            *(uint2*)&Xs[row][q * 4] = u;
        }
        __syncthreads();
        if (kc < 3) prefetch(kc + 1);

#pragma unroll
        for (int k0 = 0; k0 < 32; k0 += 16) {
            int kg = kc * 32 + k0;
            unsigned A[4][4], B[4][2];
#pragma unroll
            for (int mi = 0; mi < 4; mi++) {
                int mr = m0w + mi * 16 + lg;
                A[mi][0] = *(unsigned*)&Xs[mr][k0 + 2 * lq];
                A[mi][1] = *(unsigned*)&Xs[mr + 8][k0 + 2 * lq];
                A[mi][2] = *(unsigned*)&Xs[mr][k0 + 8 + 2 * lq];
                A[mi][3] = *(unsigned*)&Xs[mr + 8][k0 + 8 + 2 * lq];
            }
#pragma unroll
            for (int ni = 0; ni < 4; ni++) {
                int nc = n0w + ni * 8 + lg;
                B[ni][0] = *(unsigned*)&Ws[nc][kg + 2 * lq];
                B[ni][1] = *(unsigned*)&Ws[nc][kg + 8 + 2 * lq];
            }
#pragma unroll
            for (int mi = 0; mi < 4; mi++)
#pragma unroll
                for (int ni = 0; ni < 4; ni++)
                    mma_f16(acc[mi][ni], A[mi], B[ni]);
        }
        __syncthreads();
    }

#pragma unroll
    for (int mi = 0; mi < 4; mi++) {
        int r0 = m0 + m0w + mi * 16 + lg;
        int r1 = r0 + 8;
#pragma unroll
        for (int ni = 0; ni < 4; ni++) {
            int h2col = ((n0w + ni * 8) >> 1) + lq;
            if (r0 < NN)
                g_hs[(size_t)r0 * (DF / 2) + h2col] =
                    __floats2half2_rn(acc[mi][ni][0], acc[mi][ni][1]);
            if (r1 < NN)
                g_hs[(size_t)r1 * (DF / 2) + h2col] =
                    __floats2half2_rn(acc[mi][ni][2], acc[mi][ni][3]);
        }
    }
}

// ---------- fused gather-aggregate + relu + W2 GEMV (layer 1 -> gs) ----------
// one warp per dst node; each lane owns 4 features (uint2 = 4 halves).
// Inner loop batches 8 edges: 8 independent LDG.64 issued back-to-back (MLP=8).
__global__ __launch_bounds__(256) void k_agg_mid(const float* __restrict__ b1,
                                                 const float* __restrict__ W2) {
    int gt = blockIdx.x * 256 + threadIdx.x;
    int r = gt >> 5, lane = gt & 31;
    if (r >= NN) return;

    const uint2* hsv = (const uint2*)g_hs;   // 32 uint2 per row
    float di = g_dinv[r];

    uint2 sv = hsv[(size_t)r * 32 + lane];
    float2 s0 = __half22float2(*(__half2*)&sv.x);
    float2 s1 = __half22float2(*(__half2*)&sv.y);
    float ax = s0.x * di, ay = s0.y * di, az = s1.x * di, aw = s1.y * di;

    int start = g_rowstart[r];
    int len = g_cnt[r];
    for (int j0 = 0; j0 < len; j0 += 32) {
        int cnt = min(32, len - j0);
        int sidx = 0;
        float sd = 0.f;
        if (lane < cnt) {
            sidx = g_esrc[start + j0 + lane];
            sd = g_dinv[sidx];
        }
        for (int jj = 0; jj < cnt; jj += 8) {
            int si[8];
            float dd[8];
            uint2 v[8];
#pragma unroll
            for (int u = 0; u < 8; u++) {
                si[u] = __shfl_sync(FULLM, sidx, jj + u);   // jj+u <= 31
                dd[u] = __shfl_sync(FULLM, sd, jj + u);     // 0 past cnt
            }
#pragma unroll
            for (int u = 0; u < 8; u++)
                v[u] = hsv[(size_t)si[u] * 32 + lane];      // dd=0 rows add 0
#pragma unroll
            for (int u = 0; u < 8; u++) {
                float2 f0 = __half22float2(*(__half2*)&v[u].x);
                float2 f1 = __half22float2(*(__half2*)&v[u].y);
                ax = fmaf(f0.x, dd[u], ax);
                ay = fmaf(f0.y, dd[u], ay);
                az = fmaf(f1.x, dd[u], az);
                aw = fmaf(f1.y, dd[u], aw);
            }
        }
    }

    float4 bb = *(const float4*)&b1[lane * 4];
    float h0 = fmaxf(fmaf(di, ax, bb.x), 0.f);
    float h1 = fmaxf(fmaf(di, ay, bb.y), 0.f);
    float h2 = fmaxf(fmaf(di, az, bb.z), 0.f);
    float h3 = fmaxf(fmaf(di, aw, bb.w), 0.f);

    float2 w0 = *(const float2*)&W2[(size_t)(lane * 4 + 0) * 2];
    float2 w1 = *(const float2*)&W2[(size_t)(lane * 4 + 1) * 2];
    float2 w2 = *(const float2*)&W2[(size_t)(lane * 4 + 2) * 2];
    float2 w3 = *(const float2*)&W2[(size_t)(lane * 4 + 3) * 2];
    float gx = h0 * w0.x + h1 * w1.x + h2 * w2.x + h3 * w3.x;
    float gy = h0 * w0.y + h1 * w1.y + h2 * w2.y + h3 * w3.y;
#pragma unroll
    for (int off = 16; off > 0; off >>= 1) {
        gx += __shfl_xor_sync(FULLM, gx, off);
        gy += __shfl_xor_sync(FULLM, gy, off);
    }
    if (lane == 0) g_gs[r] = make_float2(gx * di, gy * di);
}

// ---------- layer-2 gather + bias -> out ----------
__global__ __launch_bounds__(256) void k_agg2(const float* __restrict__ b2,
                                              float* __restrict__ out) {
    int gt = blockIdx.x * 256 + threadIdx.x;
    int r = gt >> 5, lane = gt & 31;
    if (r >= NN) return;

    int start = g_rowstart[r];
    int len = g_cnt[r];
    float ax = 0.f, ay = 0.f;
    for (int j = lane; j < len; j += 32) {
        int s = g_esrc[start + j];
        float2 v = g_gs[s];
        ax += v.x; ay += v.y;
    }
#pragma unroll
    for (int off = 16; off > 0; off >>= 1) {
        ax += __shfl_xor_sync(FULLM, ax, off);
        ay += __shfl_xor_sync(FULLM, ay, off);
    }
    if (lane == 0) {
        float di = g_dinv[r];
        float2 self = g_gs[r];
        float2 o = make_float2(fmaf(di, self.x + ax, __ldg(&b2[0])),
                               fmaf(di, self.y + ay, __ldg(&b2[1])));
        *(float2*)&out[(size_t)r * 2] = o;
    }
}

extern "C" void kernel_launch(void* const* d_in, const int* in_sizes, int n_in,
                              void* d_out, int out_size) {
    const float* x  = (const float*)d_in[0];
    const int*   ei = (const int*)d_in[1];
    const float* W1 = (const float*)d_in[2];
    const float* b1 = (const float*)d_in[3];
    const float* W2 = (const float*)d_in[4];
    const float* b2 = (const float*)d_in[5];
    const int* src = ei;        // edge_index[0, :]
    const int* dst = ei + EE;   // edge_index[1, :]

    // fork point for side stream
    cudaEventRecord(g_ev1, 0);
    cudaStreamWaitEvent(g_s2, g_ev1, 0);

    // CSR build chain on main stream
    k_zero_cnt<<<NB, 256>>>();
    k_count<<<(EE + 255) / 256, 256>>>(dst);
    k_scan<<<NB, 256>>>();
    k_bin<<<(EE + 255) / 256, 256>>>(src, dst);

    // GEMM branch on side stream (overlaps CSR chain)
    k_wprep<<<64, 256, 0, g_s2>>>(W1);
    k_gemm1<<<(NN + 127) / 128, 256, 0, g_s2>>>(x);
    cudaEventRecord(g_ev2, g_s2);

    // join, then fused aggregation
    cudaStreamWaitEvent(0, g_ev2, 0);
    k_agg_mid<<<(NN * 32 + 255) / 256, 256>>>(b1, W2);
    k_agg2<<<(NN * 32 + 255) / 256, 256>>>(b2, (float*)d_out);
}